// round 1
// baseline (speedup 1.0000x reference)
#include <cuda_runtime.h>
#include <math.h>

#define NBB   32
#define NAA   5
#define NCC   80
#define NHH   64
#define NWW   64
#define MAXTG 50
#define CHN   (5 + NCC)          // 85
#define PLANE (NHH * NWW)        // 4096
#define NCELL (NBB * NAA * PLANE) // 655360

// -------- device scratch (no allocations allowed) --------
__device__ __align__(16) int    g_map[NCELL];
__device__ float  g_tinfo[NBB * MAXTG * 6];   // tx, ty, tw, th, tiou, gcls
__device__ float  g_gl[NBB * MAXTG];
__device__ float  g_gr[NBB * MAXTG];
__device__ float  g_gt[NBB * MAXTG];
__device__ float  g_gb[NBB * MAXTG];
__device__ float  g_ga[NBB * MAXTG];          // 0.375 * gw * gh  (SIL threshold form)
__device__ double g_loss;

__constant__ float c_anch[10] = {
    42.3f / 32.f, 55.4f / 32.f, 102.2f / 32.f, 128.3f / 32.f, 161.8f / 32.f,
    259.2f / 32.f, 303.1f / 32.f, 154.9f / 32.f, 359.6f / 32.f, 320.2f / 32.f
};

__device__ __forceinline__ float sigmoidf(float v) {
    return 1.0f / (1.0f + expf(-v));
}

// -------- kernel 0: clear map + loss --------
__global__ void k_clear() {
    int idx = blockIdx.x * blockDim.x + threadIdx.x;
    if (idx < NCELL / 4) {
        reinterpret_cast<int4*>(g_map)[idx] = make_int4(-1, -1, -1, -1);
    }
    if (idx == 0) g_loss = 0.0;
}

// -------- kernel 1: per-target precompute + scatter map --------
__global__ void k_targets(const float* __restrict__ out, const float* __restrict__ tgt) {
    int b = blockIdx.x;
    int t = threadIdx.x;
    __shared__ int nz[MAXTG];

    float cls = 0.f, fx = 0.f, fy = 0.f, fw = 0.f, fh = 0.f;
    if (t < MAXTG) {
        const float* p = tgt + (b * MAXTG + t) * 5;
        cls = p[0]; fx = p[1]; fy = p[2]; fw = p[3]; fh = p[4];
        nz[t] = (fx != 0.0f) ? 1 : 0;
    }
    __syncthreads();
    if (t >= MAXTG) return;

    // validity = cumulative AND over preceding targets (cumprod in reference)
    bool valid = true;
    for (int u = 0; u <= t; u++) valid = valid && (nz[u] != 0);

    float gx = fx * (float)NWW;
    float gy = fy * (float)NHH;
    float gw = fw * (float)NWW;
    float gh = fh * (float)NHH;

    // best anchor by anchor-IoU (first max wins, like jnp.argmax)
    int best = 0;
    float bestv = -1e30f;
#pragma unroll
    for (int a = 0; a < NAA; a++) {
        float aw = c_anch[2 * a], ah = c_anch[2 * a + 1];
        float inter = fminf(gw, aw) * fminf(gh, ah);
        float uni = gw * gh + aw * ah - inter;
        float v = inter / uni;
        if (v > bestv) { bestv = v; best = a; }
    }

    int gi = min(max((int)gx, 0), NWW - 1);
    int gj = min(max((int)gy, 0), NHH - 1);
    float awb = c_anch[2 * best], ahb = c_anch[2 * best + 1];

    const float* ob = out + (size_t)(b * (NAA * CHN) + best * CHN) * PLANE + gj * NWW + gi;
    float x = sigmoidf(ob[0]);
    float y = sigmoidf(ob[PLANE]);
    float w = ob[2 * PLANE];
    float h = ob[3 * PLANE];
    float px = x + (float)gi;
    float py = y + (float)gj;
    float pw = expf(w) * awb;
    float ph = expf(h) * ahb;

    float iw = fminf(gx + 0.5f * gw, px + 0.5f * pw) - fmaxf(gx - 0.5f * gw, px - 0.5f * pw);
    float ih = fminf(gy + 0.5f * gh, py + 0.5f * ph) - fmaxf(gy - 0.5f * gh, py - 0.5f * ph);
    float inter = fmaxf(iw, 0.f) * fmaxf(ih, 0.f);
    float uni = gw * gh + pw * ph - inter;
    float tiou = inter / uni;

    int idx = b * MAXTG + t;
    float* ti = &g_tinfo[idx * 6];
    ti[0] = gx - (float)gi;
    ti[1] = gy - (float)gj;
    ti[2] = logf(gw / awb);
    ti[3] = logf(gh / ahb);
    ti[4] = tiou;
    ti[5] = cls;

    if (valid) {
        g_gl[idx] = gx - 0.5f * gw;
        g_gr[idx] = gx + 0.5f * gw;
        g_gt[idx] = gy - 0.5f * gh;
        g_gb[idx] = gy + 0.5f * gh;
        g_ga[idx] = 0.375f * gw * gh;
        int flat = ((b * NAA + best) * NHH + gj) * NWW + gi;
        atomicMax(&g_map[flat], idx);   // last-write-wins (max t)
    } else {
        g_gl[idx] = 1e30f;  g_gr[idx] = -1e30f;
        g_gt[idx] = 1e30f;  g_gb[idx] = -1e30f;
        g_ga[idx] = 0.f;
    }
}

// -------- kernel 2: main per-cell loss --------
// grid = NBB*NAA*4 blocks; block = 256 threads; thread = 4 consecutive cells
__global__ void __launch_bounds__(256) k_main(const float* __restrict__ out) {
    __shared__ float s_gl[MAXTG], s_gr[MAXTG], s_gt[MAXTG], s_gb[MAXTG], s_ga[MAXTG];

    int blk = blockIdx.x;
    int q = blk & 3;
    int a = (blk >> 2) % NAA;
    int b = blk / (NAA * 4);
    int tid = threadIdx.x;

    if (tid < MAXTG) {
        int o = b * MAXTG + tid;
        s_gl[tid] = g_gl[o]; s_gr[tid] = g_gr[o];
        s_gt[tid] = g_gt[o]; s_gb[tid] = g_gb[o];
        s_ga[tid] = g_ga[o];
    }
    __syncthreads();

    int lin = q * 1024 + tid * 4;           // 0..4095 within (b,a) plane
    int j = lin >> 6;
    int i0 = lin & 63;

    const float* base = out + (size_t)(b * (NAA * CHN) + a * CHN) * PLANE + lin;
    float4 v0 = *reinterpret_cast<const float4*>(base);
    float4 v1 = *reinterpret_cast<const float4*>(base + PLANE);
    float4 v2 = *reinterpret_cast<const float4*>(base + 2 * PLANE);
    float4 v3 = *reinterpret_cast<const float4*>(base + 3 * PLANE);
    float4 v4 = *reinterpret_cast<const float4*>(base + 4 * PLANE);

    float o0[4] = {v0.x, v0.y, v0.z, v0.w};
    float o1[4] = {v1.x, v1.y, v1.z, v1.w};
    float o2[4] = {v2.x, v2.y, v2.z, v2.w};
    float o3[4] = {v3.x, v3.y, v3.z, v3.w};
    float o4[4] = {v4.x, v4.y, v4.z, v4.w};

    float aw = c_anch[2 * a], ah = c_anch[2 * a + 1];

    float X[4], Y[4], W[4], H[4], C[4];
    float PXL[4], PXR[4], PYT[4], PYB[4], PA[4], M[4];
#pragma unroll
    for (int k = 0; k < 4; k++) {
        X[k] = sigmoidf(o0[k]);
        Y[k] = sigmoidf(o1[k]);
        W[k] = o2[k];
        H[k] = o3[k];
        C[k] = sigmoidf(o4[k]);
        float pw = expf(W[k]) * aw;
        float ph = expf(H[k]) * ah;
        float px = X[k] + (float)(i0 + k);
        float py = Y[k] + (float)j;
        PXL[k] = px - 0.5f * pw;
        PXR[k] = px + 0.5f * pw;
        PYT[k] = py - 0.5f * ph;
        PYB[k] = py + 0.5f * ph;
        PA[k] = 0.375f * pw * ph;
        M[k] = -1e30f;
    }

    // SIL test: exists target with IoU > 0.6  <=>  inter - 0.375*(pa+ga) > 0
#pragma unroll 2
    for (int t = 0; t < MAXTG; t++) {
        float gl = s_gl[t], gr = s_gr[t], gt = s_gt[t], gb = s_gb[t], ga = s_ga[t];
#pragma unroll
        for (int k = 0; k < 4; k++) {
            float iw = fminf(PXR[k], gr) - fmaxf(PXL[k], gl);
            float ih = fminf(PYB[k], gb) - fmaxf(PYT[k], gt);
            float inter = fmaxf(iw, 0.f) * fmaxf(ih, 0.f);
            M[k] = fmaxf(M[k], inter - (PA[k] + ga));
        }
    }

    int4 sm = *reinterpret_cast<const int4*>(&g_map[(b * NAA + a) * PLANE + lin]);
    int S[4] = {sm.x, sm.y, sm.z, sm.w};

    double acc = 0.0;
#pragma unroll
    for (int k = 0; k < 4; k++) {
        if (S[k] < 0) {
            float dx = X[k] - 0.5f;
            float dy = Y[k] - 0.5f;
            float l = dx * dx + dy * dy + W[k] * W[k] + H[k] * H[k];
            float lc = (M[k] > 0.f) ? 0.f : C[k] * C[k];   // conf_mask0
            acc += 0.5 * (double)(l + lc);
        } else {
            const float* ti = &g_tinfo[S[k] * 6];
            float dx = X[k] - ti[0];
            float dy = Y[k] - ti[1];
            float dw = W[k] - ti[2];
            float dh = H[k] - ti[3];
            float dc = C[k] - ti[4];
            float l = dx * dx + dy * dy + dw * dw + dh * dh;
            acc += 0.5 * (double)l + 2.5 * (double)(dc * dc);

            // class loss: logsumexp over 80 channels - picked
            int ci = (int)ti[5];
            const float* cp = base + 5 * PLANE + k;
            float mm = -1e30f;
            for (int c = 0; c < NCC; c++) mm = fmaxf(mm, cp[c * PLANE]);
            float ssum = 0.f;
            for (int c = 0; c < NCC; c++) ssum += expf(cp[c * PLANE] - mm);
            float picked = cp[ci * PLANE];
            float lz = mm + logf(ssum);
            acc += (double)(lz - picked);
        }
    }

    // block reduction
    for (int off = 16; off > 0; off >>= 1)
        acc += __shfl_down_sync(0xffffffffu, acc, off);
    __shared__ double s_red[8];
    if ((tid & 31) == 0) s_red[tid >> 5] = acc;
    __syncthreads();
    if (tid == 0) {
        double s = 0.0;
        for (int wsl = 0; wsl < 8; wsl++) s += s_red[wsl];
        atomicAdd(&g_loss, s);
    }
}

// -------- kernel 3: write scalar --------
__global__ void k_final(float* outp) {
    outp[0] = (float)g_loss;
}

extern "C" void kernel_launch(void* const* d_in, const int* in_sizes, int n_in,
                              void* d_out, int out_size) {
    const float* out = (const float*)d_in[0];  // output (32, 425, 64, 64)
    const float* tgt = (const float*)d_in[1];  // target (32, 250)
    (void)in_sizes; (void)n_in; (void)out_size;

    k_clear<<<NCELL / 4 / 256, 256>>>();
    k_targets<<<NBB, 64>>>(out, tgt);
    k_main<<<NBB * NAA * 4, 256>>>(out);
    k_final<<<1, 1>>>((float*)d_out);
}

// round 5
// speedup vs baseline: 1.0031x; 1.0031x over previous
#include <cuda_runtime.h>
#include <math.h>

#define NBB   32
#define NAA   5
#define NCC   80
#define NHH   64
#define NWW   64
#define MAXTG 50
#define CHN   (5 + NCC)          // 85
#define PLANE (NHH * NWW)        // 4096
#define NCELL (NBB * NAA * PLANE) // 655360

// -------- device scratch (no allocations allowed) --------
__device__ __align__(16) int    g_map[NCELL];
__device__ float  g_tinfo[NBB * MAXTG * 6];   // tx, ty, tw, th, tiou, gcls
__device__ float  g_gl[NBB * MAXTG];
__device__ float  g_gr[NBB * MAXTG];
__device__ float  g_gt[NBB * MAXTG];
__device__ float  g_gb[NBB * MAXTG];
__device__ float  g_ga[NBB * MAXTG];          // 0.375 * gw * gh  (SIL threshold form)
__device__ double g_loss;

__constant__ float c_anch[10] = {
    42.3f / 32.f, 55.4f / 32.f, 102.2f / 32.f, 128.3f / 32.f, 161.8f / 32.f,
    259.2f / 32.f, 303.1f / 32.f, 154.9f / 32.f, 359.6f / 32.f, 320.2f / 32.f
};

__device__ __forceinline__ float sigmoidf(float v) {
    return 1.0f / (1.0f + expf(-v));
}

// -------- kernel 1: clear map slice + per-target precompute + scatter --------
// grid = NBB blocks, 256 threads
__global__ void k_targets(const float* __restrict__ out, const float* __restrict__ tgt) {
    int b = blockIdx.x;
    int t = threadIdx.x;

    if (b == 0 && t == 0) g_loss = 0.0;

    // clear this batch's g_map slice: NAA*PLANE = 20480 ints = 5120 int4
    {
        int4* mp = reinterpret_cast<int4*>(g_map) + b * (NAA * PLANE / 4);
        const int4 m1 = make_int4(-1, -1, -1, -1);
        for (int i = t; i < NAA * PLANE / 4; i += 256) {
            mp[i] = m1;
        }
    }

    __shared__ int nz[MAXTG];

    float cls = 0.f, fx = 0.f, fy = 0.f, fw = 0.f, fh = 0.f;
    if (t < MAXTG) {
        const float* p = tgt + (b * MAXTG + t) * 5;
        cls = p[0]; fx = p[1]; fy = p[2]; fw = p[3]; fh = p[4];
        nz[t] = (fx != 0.0f) ? 1 : 0;
    }
    __syncthreads();
    if (t >= MAXTG) return;

    // validity = cumulative AND over preceding targets (cumprod in reference)
    bool valid = true;
    for (int u = 0; u <= t; u++) valid = valid && (nz[u] != 0);

    float gx = fx * (float)NWW;
    float gy = fy * (float)NHH;
    float gw = fw * (float)NWW;
    float gh = fh * (float)NHH;

    // best anchor by anchor-IoU (first max wins, like jnp.argmax)
    int best = 0;
    float bestv = -1e30f;
#pragma unroll
    for (int a = 0; a < NAA; a++) {
        float aw = c_anch[2 * a], ah = c_anch[2 * a + 1];
        float inter = fminf(gw, aw) * fminf(gh, ah);
        float uni = gw * gh + aw * ah - inter;
        float v = inter / uni;
        if (v > bestv) { bestv = v; best = a; }
    }

    int gi = min(max((int)gx, 0), NWW - 1);
    int gj = min(max((int)gy, 0), NHH - 1);
    float awb = c_anch[2 * best], ahb = c_anch[2 * best + 1];

    const float* ob = out + (size_t)(b * (NAA * CHN) + best * CHN) * PLANE + gj * NWW + gi;
    float x = sigmoidf(ob[0]);
    float y = sigmoidf(ob[PLANE]);
    float w = ob[2 * PLANE];
    float h = ob[3 * PLANE];
    float px = x + (float)gi;
    float py = y + (float)gj;
    float pw = expf(w) * awb;
    float ph = expf(h) * ahb;

    float iw = fminf(gx + 0.5f * gw, px + 0.5f * pw) - fmaxf(gx - 0.5f * gw, px - 0.5f * pw);
    float ih = fminf(gy + 0.5f * gh, py + 0.5f * ph) - fmaxf(gy - 0.5f * gh, py - 0.5f * ph);
    float inter = fmaxf(iw, 0.f) * fmaxf(ih, 0.f);
    float uni = gw * gh + pw * ph - inter;
    float tiou = inter / uni;

    int idx = b * MAXTG + t;
    float* ti = &g_tinfo[idx * 6];
    ti[0] = gx - (float)gi;
    ti[1] = gy - (float)gj;
    ti[2] = logf(gw / awb);
    ti[3] = logf(gh / ahb);
    ti[4] = tiou;
    ti[5] = cls;

    if (valid) {
        g_gl[idx] = gx - 0.5f * gw;
        g_gr[idx] = gx + 0.5f * gw;
        g_gt[idx] = gy - 0.5f * gh;
        g_gb[idx] = gy + 0.5f * gh;
        g_ga[idx] = 0.375f * gw * gh;
        int flat = ((b * NAA + best) * NHH + gj) * NWW + gi;
        atomicMax(&g_map[flat], idx);   // last-write-wins (max t)
    } else {
        g_gl[idx] = 1e30f;  g_gr[idx] = -1e30f;
        g_gt[idx] = 1e30f;  g_gb[idx] = -1e30f;
        g_ga[idx] = 0.f;
    }
}

// -------- kernel 2: main per-cell loss --------
// grid = NBB*NAA*4 blocks; block = 256 threads; thread = 4 consecutive cells
__global__ void __launch_bounds__(256) k_main(const float* __restrict__ out) {
    __shared__ float s_gl[MAXTG], s_gr[MAXTG], s_gt[MAXTG], s_gb[MAXTG], s_ga[MAXTG];

    int blk = blockIdx.x;
    int q = blk & 3;
    int a = (blk >> 2) % NAA;
    int b = blk / (NAA * 4);
    int tid = threadIdx.x;

    if (tid < MAXTG) {
        int o = b * MAXTG + tid;
        s_gl[tid] = g_gl[o]; s_gr[tid] = g_gr[o];
        s_gt[tid] = g_gt[o]; s_gb[tid] = g_gb[o];
        s_ga[tid] = g_ga[o];
    }
    __syncthreads();

    int lin = q * 1024 + tid * 4;           // 0..4095 within (b,a) plane
    int j = lin >> 6;
    int i0 = lin & 63;

    const float* base = out + (size_t)(b * (NAA * CHN) + a * CHN) * PLANE + lin;
    float4 v0 = *reinterpret_cast<const float4*>(base);
    float4 v1 = *reinterpret_cast<const float4*>(base + PLANE);
    float4 v2 = *reinterpret_cast<const float4*>(base + 2 * PLANE);
    float4 v3 = *reinterpret_cast<const float4*>(base + 3 * PLANE);
    float4 v4 = *reinterpret_cast<const float4*>(base + 4 * PLANE);

    float o0[4] = {v0.x, v0.y, v0.z, v0.w};
    float o1[4] = {v1.x, v1.y, v1.z, v1.w};
    float o2[4] = {v2.x, v2.y, v2.z, v2.w};
    float o3[4] = {v3.x, v3.y, v3.z, v3.w};
    float o4[4] = {v4.x, v4.y, v4.z, v4.w};

    float aw = c_anch[2 * a], ah = c_anch[2 * a + 1];

    float X[4], Y[4], W[4], H[4], C[4];
    float PXL[4], PXR[4], PYT[4], PYB[4], PA[4], M[4];
#pragma unroll
    for (int k = 0; k < 4; k++) {
        X[k] = sigmoidf(o0[k]);
        Y[k] = sigmoidf(o1[k]);
        W[k] = o2[k];
        H[k] = o3[k];
        C[k] = sigmoidf(o4[k]);
        float pw = expf(W[k]) * aw;
        float ph = expf(H[k]) * ah;
        float px = X[k] + (float)(i0 + k);
        float py = Y[k] + (float)j;
        PXL[k] = px - 0.5f * pw;
        PXR[k] = px + 0.5f * pw;
        PYT[k] = py - 0.5f * ph;
        PYB[k] = py + 0.5f * ph;
        PA[k] = 0.375f * pw * ph;
        M[k] = -1e30f;
    }

    // SIL test: exists target with IoU > 0.6  <=>  inter - 0.375*(pa+ga) > 0
#pragma unroll 2
    for (int t = 0; t < MAXTG; t++) {
        float gl = s_gl[t], gr = s_gr[t], gt = s_gt[t], gb = s_gb[t], ga = s_ga[t];
#pragma unroll
        for (int k = 0; k < 4; k++) {
            float iw = fminf(PXR[k], gr) - fmaxf(PXL[k], gl);
            float ih = fminf(PYB[k], gb) - fmaxf(PYT[k], gt);
            float inter = fmaxf(iw, 0.f) * fmaxf(ih, 0.f);
            M[k] = fmaxf(M[k], inter - (PA[k] + ga));
        }
    }

    int4 sm = *reinterpret_cast<const int4*>(&g_map[(b * NAA + a) * PLANE + lin]);
    int S[4] = {sm.x, sm.y, sm.z, sm.w};

    double acc = 0.0;
#pragma unroll
    for (int k = 0; k < 4; k++) {
        if (S[k] < 0) {
            float dx = X[k] - 0.5f;
            float dy = Y[k] - 0.5f;
            float l = dx * dx + dy * dy + W[k] * W[k] + H[k] * H[k];
            float lc = (M[k] > 0.f) ? 0.f : C[k] * C[k];   // conf_mask0
            acc += 0.5 * (double)(l + lc);
        } else {
            const float* ti = &g_tinfo[S[k] * 6];
            float dx = X[k] - ti[0];
            float dy = Y[k] - ti[1];
            float dw = W[k] - ti[2];
            float dh = H[k] - ti[3];
            float dc = C[k] - ti[4];
            float l = dx * dx + dy * dy + dw * dw + dh * dh;
            acc += 0.5 * (double)l + 2.5 * (double)(dc * dc);

            // class loss: logsumexp over 80 channels - picked
            int ci = (int)ti[5];
            const float* cp = base + 5 * PLANE + k;
            float mm = -1e30f;
            for (int c = 0; c < NCC; c++) mm = fmaxf(mm, cp[c * PLANE]);
            float ssum = 0.f;
            for (int c = 0; c < NCC; c++) ssum += expf(cp[c * PLANE] - mm);
            float picked = cp[ci * PLANE];
            float lz = mm + logf(ssum);
            acc += (double)(lz - picked);
        }
    }

    // block reduction
    for (int off = 16; off > 0; off >>= 1)
        acc += __shfl_down_sync(0xffffffffu, acc, off);
    __shared__ double s_red[8];
    if ((tid & 31) == 0) s_red[tid >> 5] = acc;
    __syncthreads();
    if (tid == 0) {
        double s = 0.0;
        for (int wsl = 0; wsl < 8; wsl++) s += s_red[wsl];
        atomicAdd(&g_loss, s);
    }
}

// -------- kernel 3: write scalar --------
__global__ void k_final(float* outp) {
    outp[0] = (float)g_loss;
}

extern "C" void kernel_launch(void* const* d_in, const int* in_sizes, int n_in,
                              void* d_out, int out_size) {
    const float* out = (const float*)d_in[0];  // output (32, 425, 64, 64)
    const float* tgt = (const float*)d_in[1];  // target (32, 250)
    (void)in_sizes; (void)n_in; (void)out_size;

    k_targets<<<NBB, 256>>>(out, tgt);
    k_main<<<NBB * NAA * 4, 256>>>(out);
    k_final<<<1, 1>>>((float*)d_out);
}

// round 8
// speedup vs baseline: 1.0511x; 1.0479x over previous
#include <cuda_runtime.h>
#include <math.h>

#define NBB   32
#define NAA   5
#define NCC   80
#define NHH   64
#define NWW   64
#define MAXTG 50
#define CHN   (5 + NCC)          // 85
#define PLANE (NHH * NWW)        // 4096

__device__ double g_loss = 0.0;

__constant__ float c_anch[10] = {
    42.3f / 32.f, 55.4f / 32.f, 102.2f / 32.f, 128.3f / 32.f, 161.8f / 32.f,
    259.2f / 32.f, 303.1f / 32.f, 154.9f / 32.f, 359.6f / 32.f, 320.2f / 32.f
};

__device__ __forceinline__ float sigmoidf(float v) {
    return 1.0f / (1.0f + expf(-v));
}

// -------- fused kernel: per-block target recompute + per-cell loss --------
// grid = NBB*NAA*4 blocks; block = 256 threads; thread = 4 consecutive cells
__global__ void __launch_bounds__(256) k_main(const float* __restrict__ out,
                                              const float* __restrict__ tgt) {
    __shared__ float4 s_box[MAXTG];   // {gl, gr, gt, gb}  (box edges)
    __shared__ float2 s_misc[MAXTG];  // {-0.375*gw*gh, (float)cell or -1}
    __shared__ float  s_tx[MAXTG], s_ty[MAXTG], s_tw[MAXTG],
                      s_th[MAXTG], s_tc[MAXTG], s_tcls[MAXTG];
    __shared__ int    s_nz[MAXTG];

    int blk = blockIdx.x;
    int q = blk & 3;
    int a = (blk >> 2) % NAA;
    int b = blk / (NAA * 4);
    int tid = threadIdx.x;

    // ---- target prologue (threads 0..49) ----
    float cls = 0.f, fx = 0.f, fy = 0.f, fw = 0.f, fh = 0.f;
    if (tid < MAXTG) {
        const float* p = tgt + (b * MAXTG + tid) * 5;
        cls = p[0]; fx = p[1]; fy = p[2]; fw = p[3]; fh = p[4];
        s_nz[tid] = (fx != 0.0f) ? 1 : 0;
    }
    __syncthreads();
    if (tid < MAXTG) {
        bool valid = true;
        for (int u = 0; u <= tid; u++) valid = valid && (s_nz[u] != 0);

        float gx = fx * (float)NWW;
        float gy = fy * (float)NHH;
        float gw = fw * (float)NWW;
        float gh = fh * (float)NHH;

        // best anchor by anchor-IoU (first max wins, like jnp.argmax)
        int best = 0;
        float bestv = -1e30f;
#pragma unroll
        for (int an = 0; an < NAA; an++) {
            float aw = c_anch[2 * an], ah = c_anch[2 * an + 1];
            float inter = fminf(gw, aw) * fminf(gh, ah);
            float uni = gw * gh + aw * ah - inter;
            float v = inter / uni;
            if (v > bestv) { bestv = v; best = an; }
        }

        int gi = min(max((int)gx, 0), NWW - 1);
        int gj = min(max((int)gy, 0), NHH - 1);
        float awb = c_anch[2 * best], ahb = c_anch[2 * best + 1];

        const float* ob = out + (size_t)(b * (NAA * CHN) + best * CHN) * PLANE
                              + gj * NWW + gi;
        float xx = sigmoidf(ob[0]);
        float yy = sigmoidf(ob[PLANE]);
        float ww = ob[2 * PLANE];
        float hh = ob[3 * PLANE];
        float px = xx + (float)gi;
        float py = yy + (float)gj;
        float pw = expf(ww) * awb;
        float ph = expf(hh) * ahb;

        float iw = fminf(gx + 0.5f * gw, px + 0.5f * pw)
                 - fmaxf(gx - 0.5f * gw, px - 0.5f * pw);
        float ih = fminf(gy + 0.5f * gh, py + 0.5f * ph)
                 - fmaxf(gy - 0.5f * gh, py - 0.5f * ph);
        float inter = fmaxf(iw, 0.f) * fmaxf(ih, 0.f);
        float uni = gw * gh + pw * ph - inter;
        float tiou = inter / uni;

        s_tx[tid]   = gx - (float)gi;
        s_ty[tid]   = gy - (float)gj;
        s_tw[tid]   = logf(gw / awb);
        s_th[tid]   = logf(gh / ahb);
        s_tc[tid]   = tiou;
        s_tcls[tid] = cls;

        float cellf = (valid && best == a) ? (float)(gj * NWW + gi) : -1.0f;
        if (valid) {
            s_box[tid]  = make_float4(gx - 0.5f * gw, gx + 0.5f * gw,
                                      gy - 0.5f * gh, gy + 0.5f * gh);
            s_misc[tid] = make_float2(-0.375f * gw * gh, cellf);
        } else {
            s_box[tid]  = make_float4(1e30f, -1e30f, 1e30f, -1e30f);
            s_misc[tid] = make_float2(0.f, -1.0f);
        }
    }

    // ---- per-cell prologue (all threads; overlaps target compute latency) ----
    int lin = q * 1024 + tid * 4;           // 0..4095 within (b,a) plane
    int j = lin >> 6;
    int i0 = lin & 63;

    const float* base = out + (size_t)(b * (NAA * CHN) + a * CHN) * PLANE + lin;
    float4 v0 = *reinterpret_cast<const float4*>(base);
    float4 v1 = *reinterpret_cast<const float4*>(base + PLANE);
    float4 v2 = *reinterpret_cast<const float4*>(base + 2 * PLANE);
    float4 v3 = *reinterpret_cast<const float4*>(base + 3 * PLANE);
    float4 v4 = *reinterpret_cast<const float4*>(base + 4 * PLANE);

    float o0[4] = {v0.x, v0.y, v0.z, v0.w};
    float o1[4] = {v1.x, v1.y, v1.z, v1.w};
    float o2[4] = {v2.x, v2.y, v2.z, v2.w};
    float o3[4] = {v3.x, v3.y, v3.z, v3.w};
    float o4[4] = {v4.x, v4.y, v4.z, v4.w};

    float aw = c_anch[2 * a], ah = c_anch[2 * a + 1];

    float X[4], Y[4], W[4], H[4], C[4];
    float PXL[4], PXR[4], PYT[4], PYB[4], nPA[4], F[4];
    int   S[4];
#pragma unroll
    for (int k = 0; k < 4; k++) {
        X[k] = sigmoidf(o0[k]);
        Y[k] = sigmoidf(o1[k]);
        W[k] = o2[k];
        H[k] = o3[k];
        C[k] = sigmoidf(o4[k]);
        float pw = expf(W[k]) * aw;
        float ph = expf(H[k]) * ah;
        float px = X[k] + (float)(i0 + k);
        float py = Y[k] + (float)j;
        PXL[k] = px - 0.5f * pw;
        PXR[k] = px + 0.5f * pw;
        PYT[k] = py - 0.5f * ph;
        PYB[k] = py + 0.5f * ph;
        nPA[k] = -0.375f * pw * ph;
        F[k] = -1e30f;
        S[k] = -1;
    }

    __syncthreads();

    // ---- SIL loop + fused scatter-match ----
    // IoU>0.6  <=>  min(iw, ih, iw*ih - 0.375*(pa+ga)) > 0
    for (int t = 0; t < MAXTG; t++) {
        float4 bx = s_box[t];
        float2 mc = s_misc[t];
#pragma unroll
        for (int k = 0; k < 4; k++) {
            float iw  = fminf(PXR[k], bx.y) - fmaxf(PXL[k], bx.x);
            float ih  = fminf(PYB[k], bx.w) - fmaxf(PYT[k], bx.z);
            float nth = nPA[k] + mc.x;
            float pm  = iw * ih + nth;
            float cnd = fminf(fminf(iw, ih), pm);
            F[k] = fmaxf(F[k], cnd);
        }
        int cell = (int)mc.y;                   // exact: cell < 4096 or -1
        unsigned m = (unsigned)(cell - lin);
        if (m < 4u) {       // rare: this target scatters into one of my 4 cells
            S[0] = (m == 0u) ? t : S[0];
            S[1] = (m == 1u) ? t : S[1];
            S[2] = (m == 2u) ? t : S[2];
            S[3] = (m == 3u) ? t : S[3];
        }
    }

    // ---- per-cell epilogue ----
    double acc = 0.0;
#pragma unroll
    for (int k = 0; k < 4; k++) {
        if (S[k] < 0) {
            float dx = X[k] - 0.5f;
            float dy = Y[k] - 0.5f;
            float l = dx * dx + dy * dy + W[k] * W[k] + H[k] * H[k];
            float lc = (F[k] > 0.f) ? 0.f : C[k] * C[k];   // conf_mask0
            acc += 0.5 * (double)(l + lc);
        } else {
            int s = S[k];
            float dx = X[k] - s_tx[s];
            float dy = Y[k] - s_ty[s];
            float dw = W[k] - s_tw[s];
            float dh = H[k] - s_th[s];
            float dc = C[k] - s_tc[s];
            float l = dx * dx + dy * dy + dw * dw + dh * dh;
            acc += 0.5 * (double)l + 2.5 * (double)(dc * dc);

            // class loss: logsumexp over 80 channels - picked
            int ci = (int)s_tcls[s];
            const float* cp = base + 5 * PLANE + k;
            float mm = -1e30f;
            for (int c = 0; c < NCC; c++) mm = fmaxf(mm, cp[c * PLANE]);
            float ssum = 0.f;
            for (int c = 0; c < NCC; c++) ssum += expf(cp[c * PLANE] - mm);
            float picked = cp[ci * PLANE];
            float lz = mm + logf(ssum);
            acc += (double)(lz - picked);
        }
    }

    // ---- block reduction ----
    for (int off = 16; off > 0; off >>= 1)
        acc += __shfl_down_sync(0xffffffffu, acc, off);
    __shared__ double s_red[8];
    if ((tid & 31) == 0) s_red[tid >> 5] = acc;
    __syncthreads();
    if (tid == 0) {
        double s = 0.0;
        for (int wsl = 0; wsl < 8; wsl++) s += s_red[wsl];
        atomicAdd(&g_loss, s);
    }
}

// -------- final: write scalar, then reset accumulator for next replay --------
__global__ void k_final(float* outp) {
    outp[0] = (float)g_loss;
    g_loss = 0.0;
}

extern "C" void kernel_launch(void* const* d_in, const int* in_sizes, int n_in,
                              void* d_out, int out_size) {
    const float* out = (const float*)d_in[0];  // output (32, 425, 64, 64)
    const float* tgt = (const float*)d_in[1];  // target (32, 250)
    (void)in_sizes; (void)n_in; (void)out_size;

    k_main<<<NBB * NAA * 4, 256>>>(out, tgt);
    k_final<<<1, 1>>>((float*)d_out);
}

// round 9
// speedup vs baseline: 1.1012x; 1.0476x over previous
#include <cuda_runtime.h>
#include <math.h>

#define NBB   32
#define NAA   5
#define NCC   80
#define NHH   64
#define NWW   64
#define MAXTG 50
#define CHN   (5 + NCC)          // 85
#define PLANE (NHH * NWW)        // 4096
#define GRID_MAIN (NBB * NAA * 4) // 640
#define L2E   1.44269504088896f
#define LN2   0.69314718055995f

// -------- device scratch --------
__device__ float4   g_A[NBB * MAXTG];   // {gl, gr, gt, gb}
__device__ float4   g_B[NBB * MAXTG];   // {-0.375*gw*gh, cellg(float), tiou, cls}
__device__ float4   g_C[NBB * MAXTG];   // {tx, ty, tw, th}
__device__ double   g_loss;
__device__ unsigned g_count;

__constant__ float c_anch[10] = {
    42.3f / 32.f, 55.4f / 32.f, 102.2f / 32.f, 128.3f / 32.f, 161.8f / 32.f,
    259.2f / 32.f, 303.1f / 32.f, 154.9f / 32.f, 359.6f / 32.f, 320.2f / 32.f
};

__device__ __forceinline__ float sigf(float v) {
    return 1.0f / (1.0f + exp2f(v * -L2E));
}

// -------- kernel 1: per-target precompute (32 blocks x 64 threads) --------
__global__ void __launch_bounds__(64) k_targets(const float* __restrict__ out,
                                                const float* __restrict__ tgt) {
    int b = blockIdx.x;
    int t = threadIdx.x;

    if (b == 0 && t == 0) { g_loss = 0.0; g_count = 0u; }

    float cls = 0.f, fx = 0.f, fy = 0.f, fw = 0.f, fh = 0.f;
    bool nzf = true;
    if (t < MAXTG) {
        const float* p = tgt + (b * MAXTG + t) * 5;
        cls = p[0]; fx = p[1]; fy = p[2]; fw = p[3]; fh = p[4];
        nzf = (fx != 0.0f);
    }

    // first index with fx==0 via ballot (validity = t < first_zero)
    __shared__ unsigned zmask[2];
    unsigned zeros = __ballot_sync(0xffffffffu, !nzf);
    if ((t & 31) == 0) zmask[t >> 5] = zeros;
    __syncthreads();
    int fz0 = __ffs((int)zmask[0]);
    int fz1 = __ffs((int)zmask[1]);
    int first_zero = fz0 ? (fz0 - 1) : (fz1 ? 32 + fz1 - 1 : 1000);

    if (t >= MAXTG) return;
    bool valid = t < first_zero;

    float gx = fx * (float)NWW;
    float gy = fy * (float)NHH;
    float gw = fw * (float)NWW;
    float gh = fh * (float)NHH;

    // best anchor by anchor-IoU (first max wins)
    int best = 0;
    float bestv = -1e30f;
#pragma unroll
    for (int an = 0; an < NAA; an++) {
        float aw = c_anch[2 * an], ah = c_anch[2 * an + 1];
        float inter = fminf(gw, aw) * fminf(gh, ah);
        float uni = gw * gh + aw * ah - inter;
        float v = inter / uni;
        if (v > bestv) { bestv = v; best = an; }
    }

    int gi = min(max((int)gx, 0), NWW - 1);
    int gj = min(max((int)gy, 0), NHH - 1);
    float awb = c_anch[2 * best], ahb = c_anch[2 * best + 1];

    const float* ob = out + (size_t)(b * (NAA * CHN) + best * CHN) * PLANE
                          + gj * NWW + gi;
    float xx = sigf(ob[0]);
    float yy = sigf(ob[PLANE]);
    float ww = ob[2 * PLANE];
    float hh = ob[3 * PLANE];
    float px = xx + (float)gi;
    float py = yy + (float)gj;
    float pw = exp2f(ww * L2E) * awb;
    float ph = exp2f(hh * L2E) * ahb;

    float iw = fminf(gx + 0.5f * gw, px + 0.5f * pw)
             - fmaxf(gx - 0.5f * gw, px - 0.5f * pw);
    float ih = fminf(gy + 0.5f * gh, py + 0.5f * ph)
             - fmaxf(gy - 0.5f * gh, py - 0.5f * ph);
    float inter = fmaxf(iw, 0.f) * fmaxf(ih, 0.f);
    float uni = gw * gh + pw * ph - inter;
    float tiou = inter / uni;

    int idx = b * MAXTG + t;
    g_C[idx] = make_float4(gx - (float)gi, gy - (float)gj,
                           log2f(gw / awb) * LN2, log2f(gh / ahb) * LN2);

    float cellg = valid ? (float)(best * PLANE + gj * NWW + gi) : -1.0f;
    if (valid) {
        g_A[idx] = make_float4(gx - 0.5f * gw, gx + 0.5f * gw,
                               gy - 0.5f * gh, gy + 0.5f * gh);
        g_B[idx] = make_float4(-0.375f * gw * gh, cellg, tiou, cls);
    } else {
        g_A[idx] = make_float4(1e30f, -1e30f, 1e30f, -1e30f);
        g_B[idx] = make_float4(0.f, -1.0f, tiou, cls);
    }
}

// -------- kernel 2: per-cell loss + fused final write --------
// grid = 640 blocks; block = 256 threads; thread = 4 consecutive cells
__global__ void __launch_bounds__(256) k_main(const float* __restrict__ out,
                                              float* __restrict__ outp) {
    __shared__ float4 s_A[MAXTG];     // box edges
    __shared__ float4 s_B[MAXTG];     // {nga, cellg, tiou, cls}

    int blk = blockIdx.x;
    int q = blk & 3;
    int a = (blk >> 2) % NAA;
    int b = blk / (NAA * 4);
    int tid = threadIdx.x;

    if (tid < MAXTG) {
        int o = b * MAXTG + tid;
        s_A[tid] = g_A[o];
        s_B[tid] = g_B[o];
    }

    int lin = q * 1024 + tid * 4;           // 0..4095 within (b,a) plane
    int j = lin >> 6;
    int i0 = lin & 63;
    int alin = a * PLANE + lin;             // anchor-global cell base

    const float* base = out + (size_t)(b * (NAA * CHN) + a * CHN) * PLANE + lin;
    float4 v0 = *reinterpret_cast<const float4*>(base);
    float4 v1 = *reinterpret_cast<const float4*>(base + PLANE);
    float4 v2 = *reinterpret_cast<const float4*>(base + 2 * PLANE);
    float4 v3 = *reinterpret_cast<const float4*>(base + 3 * PLANE);
    float4 v4 = *reinterpret_cast<const float4*>(base + 4 * PLANE);

    float o0[4] = {v0.x, v0.y, v0.z, v0.w};
    float o1[4] = {v1.x, v1.y, v1.z, v1.w};
    float o2[4] = {v2.x, v2.y, v2.z, v2.w};
    float o3[4] = {v3.x, v3.y, v3.z, v3.w};
    float o4[4] = {v4.x, v4.y, v4.z, v4.w};

    float aw = c_anch[2 * a], ah = c_anch[2 * a + 1];

    float X[4], Y[4], W[4], H[4], C[4];
    float PXL[4], PXR[4], PYT[4], PYB[4], nPA[4], F[4];
    int   S[4];
#pragma unroll
    for (int k = 0; k < 4; k++) {
        X[k] = sigf(o0[k]);
        Y[k] = sigf(o1[k]);
        W[k] = o2[k];
        H[k] = o3[k];
        C[k] = sigf(o4[k]);
        float pw = exp2f(W[k] * L2E) * aw;
        float ph = exp2f(H[k] * L2E) * ah;
        float px = X[k] + (float)(i0 + k);
        float py = Y[k] + (float)j;
        PXL[k] = px - 0.5f * pw;
        PXR[k] = px + 0.5f * pw;
        PYT[k] = py - 0.5f * ph;
        PYB[k] = py + 0.5f * ph;
        nPA[k] = -0.375f * pw * ph;
        F[k] = -1e30f;
        S[k] = -1;
    }

    __syncthreads();

    // SIL loop + fused scatter-match
    // IoU>0.6  <=>  min(iw, ih, iw*ih - 0.375*(pa+ga)) > 0
#pragma unroll 5
    for (int t = 0; t < MAXTG; t++) {
        float4 bx = s_A[t];
        float4 mb = s_B[t];
#pragma unroll
        for (int k = 0; k < 4; k++) {
            float iw  = fminf(PXR[k], bx.y) - fmaxf(PXL[k], bx.x);
            float ih  = fminf(PYB[k], bx.w) - fmaxf(PYT[k], bx.z);
            float nth = nPA[k] + mb.x;
            float pm  = iw * ih + nth;
            float cnd = fminf(fminf(iw, ih), pm);
            F[k] = fmaxf(F[k], cnd);
        }
        int cellg = (int)mb.y;                  // exact integer or -1
        unsigned m = (unsigned)(cellg - alin);
        if (m < 4u) {
            S[0] = (m == 0u) ? t : S[0];
            S[1] = (m == 1u) ? t : S[1];
            S[2] = (m == 2u) ? t : S[2];
            S[3] = (m == 3u) ? t : S[3];
        }
    }

    // per-cell epilogue
    double acc = 0.0;
#pragma unroll
    for (int k = 0; k < 4; k++) {
        if (S[k] < 0) {
            float dx = X[k] - 0.5f;
            float dy = Y[k] - 0.5f;
            float l = dx * dx + dy * dy + W[k] * W[k] + H[k] * H[k];
            float lc = (F[k] > 0.f) ? 0.f : C[k] * C[k];
            acc += 0.5 * (double)(l + lc);
        } else {
            int s = S[k];
            float4 tc = g_C[b * MAXTG + s];     // rare: L2 load
            float4 mb = s_B[s];
            float dx = X[k] - tc.x;
            float dy = Y[k] - tc.y;
            float dw = W[k] - tc.z;
            float dh = H[k] - tc.w;
            float dc = C[k] - mb.z;
            float l = dx * dx + dy * dy + dw * dw + dh * dh;
            acc += 0.5 * (double)l + 2.5 * (double)(dc * dc);

            // class loss: logsumexp over 80 channels - picked
            int ci = (int)mb.w;
            const float* cp = base + 5 * PLANE + k;
            float mm = -1e30f;
            for (int c = 0; c < NCC; c++) mm = fmaxf(mm, cp[c * PLANE]);
            float ssum = 0.f;
            for (int c = 0; c < NCC; c++) ssum += exp2f((cp[c * PLANE] - mm) * L2E);
            float picked = cp[ci * PLANE];
            float lz = mm + log2f(ssum) * LN2;
            acc += (double)(lz - picked);
        }
    }

    // block reduction
    for (int off = 16; off > 0; off >>= 1)
        acc += __shfl_down_sync(0xffffffffu, acc, off);
    __shared__ double s_red[8];
    if ((tid & 31) == 0) s_red[tid >> 5] = acc;
    __syncthreads();
    if (tid == 0) {
        double s = 0.0;
        for (int wsl = 0; wsl < 8; wsl++) s += s_red[wsl];
        atomicAdd(&g_loss, s);
        __threadfence();
        unsigned old = atomicAdd(&g_count, 1u);
        if (old == (unsigned)(GRID_MAIN - 1)) {
            double total = *(volatile double*)&g_loss;
            outp[0] = (float)total;
        }
    }
}

extern "C" void kernel_launch(void* const* d_in, const int* in_sizes, int n_in,
                              void* d_out, int out_size) {
    const float* out = (const float*)d_in[0];  // output (32, 425, 64, 64)
    const float* tgt = (const float*)d_in[1];  // target (32, 250)
    (void)in_sizes; (void)n_in; (void)out_size;

    k_targets<<<NBB, 64>>>(out, tgt);
    k_main<<<GRID_MAIN, 256>>>(out, (float*)d_out);
}